// round 16
// baseline (speedup 1.0000x reference)
#include <cuda_runtime.h>
#include <cuda_fp16.h>
#include <cstdint>

#define N_NODES 16384
#define A_ANCH  256
#define D_LAT   32

// B fragments for mma.m16n8k16.f16 (M UNSCALED; 1/256 applied in epilogue):
//   g_Bfrag16[((ks*4 + nt)*32 + lane)] = {b0_hi, b1_hi, b0_lo, b1_lo} (half2)
//   b0 = {M[k0][col], M[k0+1][col]}, b1 = {M[k0+8][col], M[k0+9][col]}
//   k0 = ks*16 + 2*(lane&3), col = nt*8 + (lane>>2).
__device__ uint4 g_Bfrag16[16 * 4 * 32];   // 32 KB
__device__ float g_c[D_LAT];

#define PACK_H2(dst, flo, fhi) \
    asm("cvt.rn.f16x2.f32 %0, %1, %2;" : "=r"(dst) : "f"(fhi), "f"(flo))

__device__ __forceinline__ float2 h2f2(unsigned u) {
    __half2 h = *reinterpret_cast<__half2*>(&u);
    return __half22float2(h);
}

// ---------------------------------------------------------------------------
// Kernel 1: precompute fp16 B fragments (hi/lo split) + c (validated R15).
// ---------------------------------------------------------------------------
__global__ __launch_bounds__(256) void precompute_kernel(
    const float* __restrict__ embeds,
    const float* __restrict__ W,       // [64,32]: W1 rows 0..31, W2 rows 32..63
    const float* __restrict__ b,
    const int*   __restrict__ anchor_ids)
{
    __shared__ float Wsh[D_LAT * D_LAT];
    __shared__ float esh[32][32];
    __shared__ float Ms[32][33];
    __shared__ float ssh[D_LAT];

    const int t   = threadIdx.x;
    const int blk = blockIdx.x;
    const int j   = t & 31;

    if (blk < 8) {
        #pragma unroll
        for (int i = t; i < D_LAT * D_LAT; i += 256) Wsh[i] = W[i];
        for (int r = t >> 5; r < 32; r += 8) {
            int id = anchor_ids[blk * 32 + r];
            esh[r][j] = embeds[id * D_LAT + j];
        }
        __syncthreads();
        for (int r = t >> 5; r < 32; r += 8) {
            float acc = 0.f;
            #pragma unroll
            for (int d = 0; d < D_LAT; d++) acc += esh[r][d] * Wsh[d * D_LAT + j];
            Ms[r][j] = acc;                      // UNSCALED
        }
        __syncthreads();
        {
            int lane = t & 31;
            int nt   = (t >> 5) & 3;
            int kl   = t >> 7;                   // 0 or 1
            int k0l  = kl * 16 + 2 * (lane & 3);
            int col  = nt * 8 + (lane >> 2);
            float f0 = Ms[k0l][col];
            float f1 = Ms[k0l + 1][col];
            float f2 = Ms[k0l + 8][col];
            float f3 = Ms[k0l + 9][col];
            unsigned b0h, b1h, b0l, b1l;
            PACK_H2(b0h, f0, f1);
            PACK_H2(b1h, f2, f3);
            float2 r0 = h2f2(b0h), r1 = h2f2(b1h);
            PACK_H2(b0l, f0 - r0.x, f1 - r0.y);
            PACK_H2(b1l, f2 - r1.x, f3 - r1.y);
            int ks = 2 * blk + kl;
            g_Bfrag16[(ks * 4 + nt) * 32 + lane] = make_uint4(b0h, b1h, b0l, b1l);
        }
    } else {
        #pragma unroll
        for (int i = t; i < D_LAT * D_LAT; i += 256) Wsh[i] = W[D_LAT * D_LAT + i];
        if (t < D_LAT) ssh[t] = 0.f;
        __syncthreads();
        {
            int grp = t >> 5;
            float part = 0.f;
            #pragma unroll
            for (int i = 0; i < 32; i++)
                part += embeds[(grp * 32 + i) * D_LAT + j];
            atomicAdd(&ssh[j], part);
        }
        __syncthreads();
        if (t < D_LAT) {
            float acc = 0.f;
            #pragma unroll
            for (int d = 0; d < D_LAT; d++) acc += ssh[d] * Wsh[d * D_LAT + t];
            g_c[t] = b[t] + acc * (1.0f / 256.0f);
        }
    }
}

// ---------------------------------------------------------------------------
// Kernel 2: out = (dists^T @ M)/256 + c via mma.m16n8k16.f16 (3-pass split).
// 128 blocks x 128 n: each DRAM touch is 512 B contiguous per k-row
// (4x activation efficiency vs the 128-B slices of all prior rounds).
// 8 warps; warp w owns rows w*16..w*16+15, FULL K=256 (no reduction).
// K pipelined as 8 slabs of 32 k-rows through a 3-stage cp.async ring
// (16 KB/stage); prologue stages issued before the PDL grid sync.
// ---------------------------------------------------------------------------
#define SROW     132                       // floats per k-row in smem (128+4)
#define STAGE_F  (32 * SROW)               // 4224 floats
#define STAGE_B  (STAGE_F * 4)             // 16896 bytes
#define SMEM_B   (3 * STAGE_B)             // 50688 bytes

#define MMAH(AC, A0, A1, A2, A3, B0, B1)                                      \
    asm("mma.sync.aligned.m16n8k16.row.col.f32.f16.f16.f32 "                  \
        "{%0,%1,%2,%3},{%4,%5,%6,%7},{%8,%9},{%0,%1,%2,%3};"                  \
        : "+f"(AC[0]), "+f"(AC[1]), "+f"(AC[2]), "+f"(AC[3])                  \
        : "r"(A0), "r"(A1), "r"(A2), "r"(A3), "r"(B0), "r"(B1));

__global__ __launch_bounds__(256) void pnn_mma_kernel(
    const float* __restrict__ dists,   // [A, N]
    float*       __restrict__ out)     // [N, 32]
{
    extern __shared__ __align__(16) float Asm[];   // 3 stages

    const int t    = threadIdx.x;
    const int lane = t & 31;
    const int w    = t >> 5;
    const int n0   = blockIdx.x * 128;

    uint32_t sbase;
    asm("{ .reg .u64 tmp; cvta.to.shared.u64 tmp, %1; cvt.u32.u64 %0, tmp; }"
        : "=r"(sbase) : "l"(Asm));

    const int chunk = t & 31;          // 16B chunk within 512-B row span
    const int kr0   = t >> 5;          // 0..7

    // issue slab s into ring buffer buf
    #define ISSUE(s, buf) {                                                       \
        _Pragma("unroll")                                                         \
        for (int i_ = 0; i_ < 4; i_++) {                                          \
            int krl_ = kr0 + 8 * i_;                                              \
            const float* src_ = dists + (size_t)((s) * 32 + krl_) * N_NODES       \
                                      + n0 + chunk * 4;                           \
            uint32_t dst_ = sbase + (buf) * STAGE_B + krl_ * (SROW * 4)           \
                                  + chunk * 16;                                   \
            asm volatile("cp.async.ca.shared.global [%0], [%1], 16;"              \
                         :: "r"(dst_), "l"(src_) : "memory");                     \
        }                                                                         \
        asm volatile("cp.async.commit_group;" ::: "memory");                      \
    }

    // ---- prologue: 3 stages in flight BEFORE the PDL grid sync ----
    ISSUE(0, 0)
    ISSUE(1, 1)
    ISSUE(2, 2)

    cudaGridDependencySynchronize();

    float acc[4][4];
    #pragma unroll
    for (int i = 0; i < 4; i++)
        #pragma unroll
        for (int k = 0; k < 4; k++) acc[i][k] = 0.f;

    const int rn = w * 16 + (lane >> 2);   // local n row within block
    const int c2 = 2 * (lane & 3);

    #define STEP(S, K0, FB) {                                                     \
        float v00 = (S)[(K0 + c2)     * SROW + rn];                               \
        float v01 = (S)[(K0 + c2 + 1) * SROW + rn];                               \
        float v10 = (S)[(K0 + c2)     * SROW + rn + 8];                           \
        float v11 = (S)[(K0 + c2 + 1) * SROW + rn + 8];                           \
        float v20 = (S)[(K0 + c2 + 8) * SROW + rn];                               \
        float v21 = (S)[(K0 + c2 + 9) * SROW + rn];                               \
        float v30 = (S)[(K0 + c2 + 8) * SROW + rn + 8];                           \
        float v31 = (S)[(K0 + c2 + 9) * SROW + rn + 8];                           \
        unsigned ah0, ah1, ah2, ah3, al0, al1, al2, al3;                          \
        PACK_H2(ah0, v00, v01);                                                   \
        PACK_H2(ah1, v10, v11);                                                   \
        PACK_H2(ah2, v20, v21);                                                   \
        PACK_H2(ah3, v30, v31);                                                   \
        { float2 r = h2f2(ah0); PACK_H2(al0, v00 - r.x, v01 - r.y); }             \
        { float2 r = h2f2(ah1); PACK_H2(al1, v10 - r.x, v11 - r.y); }             \
        { float2 r = h2f2(ah2); PACK_H2(al2, v20 - r.x, v21 - r.y); }             \
        { float2 r = h2f2(ah3); PACK_H2(al3, v30 - r.x, v31 - r.y); }             \
        _Pragma("unroll")                                                         \
        for (int nt = 0; nt < 4; nt++) {                                          \
            MMAH(acc[nt], ah0, ah1, ah2, ah3, FB[nt].x, FB[nt].y);                \
            MMAH(acc[nt], ah0, ah1, ah2, ah3, FB[nt].z, FB[nt].w);                \
            MMAH(acc[nt], al0, al1, al2, al3, FB[nt].x, FB[nt].y);                \
        }                                                                         \
    }

    for (int s = 0; s < 8; s++) {
        const int buf = s % 3;

        // B fragments for ksteps 2s, 2s+1 (L1/L2-hot after first slab)
        const uint4* pb = g_Bfrag16 + lane;
        uint4 fb0[4], fb1[4];
        #pragma unroll
        for (int nt = 0; nt < 4; nt++) {
            fb0[nt] = pb[((2 * s)     * 4 + nt) << 5];
            fb1[nt] = pb[((2 * s + 1) * 4 + nt) << 5];
        }

        if (s < 6)      asm volatile("cp.async.wait_group 2;" ::: "memory");
        else if (s == 6) asm volatile("cp.async.wait_group 1;" ::: "memory");
        else             asm volatile("cp.async.wait_group 0;" ::: "memory");
        __syncthreads();

        const float* S = Asm + buf * STAGE_F;
        STEP(S, 0,  fb0)
        STEP(S, 16, fb1)

        __syncthreads();           // everyone done reading buf
        if (s + 3 < 8) ISSUE(s + 3, buf)
    }
    #undef STEP
    #undef ISSUE

    // ---- epilogue: scale 1/256, add c, direct stores ----
    const int r0 = n0 + w * 16 + (lane >> 2);
    #pragma unroll
    for (int nt = 0; nt < 4; nt++) {
        int col = nt * 8 + 2 * (lane & 3);
        float2 cc = *(const float2*)(g_c + col);
        float2 v0 = make_float2(acc[nt][0] * (1.0f / 256.0f) + cc.x,
                                acc[nt][1] * (1.0f / 256.0f) + cc.y);
        float2 v1 = make_float2(acc[nt][2] * (1.0f / 256.0f) + cc.x,
                                acc[nt][3] * (1.0f / 256.0f) + cc.y);
        *(float2*)(out + (size_t)r0 * D_LAT + col)       = v0;
        *(float2*)(out + (size_t)(r0 + 8) * D_LAT + col) = v1;
    }
}

extern "C" void kernel_launch(void* const* d_in, const int* in_sizes, int n_in,
                              void* d_out, int out_size)
{
    const float* embeds     = (const float*)d_in[0];
    const float* dists      = (const float*)d_in[1];
    const float* W_hidden   = (const float*)d_in[2];
    const float* b_hidden   = (const float*)d_in[3];
    const int*   anchor_ids = (const int*)  d_in[4];
    float*       out        = (float*)d_out;

    cudaFuncSetAttribute(pnn_mma_kernel,
                         cudaFuncAttributeMaxDynamicSharedMemorySize, SMEM_B);

    precompute_kernel<<<9, 256>>>(embeds, W_hidden, b_hidden, anchor_ids);

    cudaLaunchConfig_t cfg = {};
    cfg.gridDim  = dim3(N_NODES / 128, 1, 1);
    cfg.blockDim = dim3(256, 1, 1);
    cfg.dynamicSmemBytes = SMEM_B;
    cfg.stream = 0;
    cudaLaunchAttribute attr[1];
    attr[0].id = cudaLaunchAttributeProgrammaticStreamSerialization;
    attr[0].val.programmaticStreamSerializationAllowed = 1;
    cfg.attrs = attr;
    cfg.numAttrs = 1;

    cudaError_t e = cudaLaunchKernelEx(&cfg, pnn_mma_kernel, dists, out);
    if (e != cudaSuccess) {
        pnn_mma_kernel<<<N_NODES / 128, 256, SMEM_B>>>(dists, out);
    }
}

// round 17
// speedup vs baseline: 1.0151x; 1.0151x over previous
#include <cuda_runtime.h>
#include <cuda_fp16.h>
#include <cstdint>

#define N_NODES 16384
#define A_ANCH  256
#define D_LAT   32

// B fragments for mma.m16n8k16.f16 (M UNSCALED; 1/256 applied in epilogue):
//   g_Bfrag16[((ks*4 + nt)*32 + lane)] = {b0_hi, b1_hi, b0_lo, b1_lo} (half2)
__device__ uint4 g_Bfrag16[16 * 4 * 32];   // 32 KB
__device__ float g_c[D_LAT];

#define PACK_H2(dst, flo, fhi) \
    asm("cvt.rn.f16x2.f32 %0, %1, %2;" : "=r"(dst) : "f"(fhi), "f"(flo))

__device__ __forceinline__ float2 h2f2(unsigned u) {
    __half2 h = *reinterpret_cast<__half2*>(&u);
    return __half22float2(h);
}

// ---------------------------------------------------------------------------
// Kernel 1: precompute fp16 B fragments (hi/lo split) + c (validated R15).
// ---------------------------------------------------------------------------
__global__ __launch_bounds__(256) void precompute_kernel(
    const float* __restrict__ embeds,
    const float* __restrict__ W,       // [64,32]: W1 rows 0..31, W2 rows 32..63
    const float* __restrict__ b,
    const int*   __restrict__ anchor_ids)
{
    __shared__ float Wsh[D_LAT * D_LAT];
    __shared__ float esh[32][32];
    __shared__ float Ms[32][33];
    __shared__ float ssh[D_LAT];

    const int t   = threadIdx.x;
    const int blk = blockIdx.x;
    const int j   = t & 31;

    if (blk < 8) {
        #pragma unroll
        for (int i = t; i < D_LAT * D_LAT; i += 256) Wsh[i] = W[i];
        for (int r = t >> 5; r < 32; r += 8) {
            int id = anchor_ids[blk * 32 + r];
            esh[r][j] = embeds[id * D_LAT + j];
        }
        __syncthreads();
        for (int r = t >> 5; r < 32; r += 8) {
            float acc = 0.f;
            #pragma unroll
            for (int d = 0; d < D_LAT; d++) acc += esh[r][d] * Wsh[d * D_LAT + j];
            Ms[r][j] = acc;                      // UNSCALED
        }
        __syncthreads();
        {
            int lane = t & 31;
            int nt   = (t >> 5) & 3;
            int kl   = t >> 7;                   // 0 or 1
            int k0l  = kl * 16 + 2 * (lane & 3);
            int col  = nt * 8 + (lane >> 2);
            float f0 = Ms[k0l][col];
            float f1 = Ms[k0l + 1][col];
            float f2 = Ms[k0l + 8][col];
            float f3 = Ms[k0l + 9][col];
            unsigned b0h, b1h, b0l, b1l;
            PACK_H2(b0h, f0, f1);
            PACK_H2(b1h, f2, f3);
            float2 r0 = h2f2(b0h), r1 = h2f2(b1h);
            PACK_H2(b0l, f0 - r0.x, f1 - r0.y);
            PACK_H2(b1l, f2 - r1.x, f3 - r1.y);
            int ks = 2 * blk + kl;
            g_Bfrag16[(ks * 4 + nt) * 32 + lane] = make_uint4(b0h, b1h, b0l, b1l);
        }
    } else {
        #pragma unroll
        for (int i = t; i < D_LAT * D_LAT; i += 256) Wsh[i] = W[D_LAT * D_LAT + i];
        if (t < D_LAT) ssh[t] = 0.f;
        __syncthreads();
        {
            int grp = t >> 5;
            float part = 0.f;
            #pragma unroll
            for (int i = 0; i < 32; i++)
                part += embeds[(grp * 32 + i) * D_LAT + j];
            atomicAdd(&ssh[j], part);
        }
        __syncthreads();
        if (t < D_LAT) {
            float acc = 0.f;
            #pragma unroll
            for (int d = 0; d < D_LAT; d++) acc += ssh[d] * Wsh[d * D_LAT + t];
            g_c[t] = b[t] + acc * (1.0f / 256.0f);
        }
    }
}

// ---------------------------------------------------------------------------
// Kernel 2: out = (dists^T @ M)/256 + c via mma.m16n8k16.f16 (3-pass split).
// Grid 512 x 256 thr. Block covers 32 n x FULL K=256.
// A tile (32 KB) staged via 256 cp.async.bulk row copies (one per thread,
// 128 B each) issued BEFORE the PDL grid sync, completing on ONE mbarrier
// (expect_tx 32768). ~4 blocks/SM resident => ~16 MB in flight chip-wide.
// Compute: 8 warps = 2 rtile x 4 kg, validated R15 fragments; smem reduce.
// ---------------------------------------------------------------------------
#define SROW    36                         // floats per k-row (32 + 4 pad)
#define SMEM_B  (256 * SROW * 4)           // 36864 bytes

#define MMAH(AC, A0, A1, A2, A3, B0, B1)                                      \
    asm("mma.sync.aligned.m16n8k16.row.col.f32.f16.f16.f32 "                  \
        "{%0,%1,%2,%3},{%4,%5,%6,%7},{%8,%9},{%0,%1,%2,%3};"                  \
        : "+f"(AC[0]), "+f"(AC[1]), "+f"(AC[2]), "+f"(AC[3])                  \
        : "r"(A0), "r"(A1), "r"(A2), "r"(A3), "r"(B0), "r"(B1));

__global__ __launch_bounds__(256) void pnn_mma_kernel(
    const float* __restrict__ dists,   // [A, N]
    float*       __restrict__ out)     // [N, 32]
{
    extern __shared__ __align__(16) float Asm[];   // [256][SROW]
    __shared__ __align__(8) unsigned long long mbar;

    const int t    = threadIdx.x;
    const int lane = t & 31;
    const int w    = t >> 5;
    const int rtile = w & 1;
    const int kg    = w >> 1;          // 0..3
    const int n0   = blockIdx.x * 32;

    uint32_t sbase, mbar_a;
    asm("{ .reg .u64 tmp; cvta.to.shared.u64 tmp, %1; cvt.u32.u64 %0, tmp; }"
        : "=r"(sbase) : "l"(Asm));
    asm("{ .reg .u64 tmp; cvta.to.shared.u64 tmp, %1; cvt.u32.u64 %0, tmp; }"
        : "=r"(mbar_a) : "l"(&mbar));

    // ---- mbarrier init + expect_tx, then ALL row copies (before PDL sync) ----
    if (t == 0) {
        asm volatile("mbarrier.init.shared.b64 [%0], %1;"
                     :: "r"(mbar_a), "r"(1u) : "memory");
        asm volatile("mbarrier.arrive.expect_tx.shared.b64 _, [%0], %1;"
                     :: "r"(mbar_a), "r"(32768u) : "memory");
    }
    __syncthreads();
    {
        const float* src = dists + (size_t)t * N_NODES + n0;   // row t, 128 B
        uint32_t dst = sbase + t * (SROW * 4);
        asm volatile(
            "cp.async.bulk.shared::cta.global.mbarrier::complete_tx::bytes "
            "[%0], [%1], %2, [%3];"
            :: "r"(dst), "l"(src), "r"(128u), "r"(mbar_a) : "memory");
    }

    // ---- wait for precompute results (PDL); B frags load during DMA wait ----
    cudaGridDependencySynchronize();

    const uint4* pb = g_Bfrag16 + (size_t)(kg * 4 * 4) * 32 + lane;
    uint4 fbA[4], fbB[4];
    #pragma unroll
    for (int nt = 0; nt < 4; nt++) {
        fbA[nt] = pb[(0 * 4 + nt) << 5];
        fbB[nt] = pb[(1 * 4 + nt) << 5];
    }

    // ---- wait for the A tile DMA ----
    {
        unsigned done;
        asm volatile(
            "{\n\t.reg .pred p;\n\t"
            "mbarrier.try_wait.parity.acquire.cta.shared::cta.b64 p, [%1], 0;\n\t"
            "selp.b32 %0, 1, 0, p;\n\t}"
            : "=r"(done) : "r"(mbar_a) : "memory");
        if (!done) {
            asm volatile(
                "{\n\t.reg .pred P1;\n\t"
                "WL_%=:\n\t"
                "mbarrier.try_wait.parity.acquire.cta.shared::cta.b64 P1, [%0], 0, 0x989680;\n\t"
                "@P1 bra.uni WD_%=;\n\t"
                "bra.uni WL_%=;\n\t"
                "WD_%=:\n\t}"
                :: "r"(mbar_a) : "memory");
        }
    }

    float acc[4][4];
    #pragma unroll
    for (int i = 0; i < 4; i++)
        #pragma unroll
        for (int k = 0; k < 4; k++) acc[i][k] = 0.f;

    const int rn = rtile * 16 + (lane >> 2);
    const int c2 = 2 * (lane & 3);

    #define STEP(jj, FB) {                                                        \
        const int K0 = (kg * 4 + (jj)) * 16;                                      \
        float v00 = Asm[(K0 + c2)     * SROW + rn];                               \
        float v01 = Asm[(K0 + c2 + 1) * SROW + rn];                               \
        float v10 = Asm[(K0 + c2)     * SROW + rn + 8];                           \
        float v11 = Asm[(K0 + c2 + 1) * SROW + rn + 8];                           \
        float v20 = Asm[(K0 + c2 + 8) * SROW + rn];                               \
        float v21 = Asm[(K0 + c2 + 9) * SROW + rn];                               \
        float v30 = Asm[(K0 + c2 + 8) * SROW + rn + 8];                           \
        float v31 = Asm[(K0 + c2 + 9) * SROW + rn + 8];                           \
        unsigned ah0, ah1, ah2, ah3, al0, al1, al2, al3;                          \
        PACK_H2(ah0, v00, v01);                                                   \
        PACK_H2(ah1, v10, v11);                                                   \
        PACK_H2(ah2, v20, v21);                                                   \
        PACK_H2(ah3, v30, v31);                                                   \
        { float2 r = h2f2(ah0); PACK_H2(al0, v00 - r.x, v01 - r.y); }             \
        { float2 r = h2f2(ah1); PACK_H2(al1, v10 - r.x, v11 - r.y); }             \
        { float2 r = h2f2(ah2); PACK_H2(al2, v20 - r.x, v21 - r.y); }             \
        { float2 r = h2f2(ah3); PACK_H2(al3, v30 - r.x, v31 - r.y); }             \
        _Pragma("unroll")                                                         \
        for (int nt = 0; nt < 4; nt++) {                                          \
            MMAH(acc[nt], ah0, ah1, ah2, ah3, FB[nt].x, FB[nt].y);                \
            MMAH(acc[nt], ah0, ah1, ah2, ah3, FB[nt].z, FB[nt].w);                \
            MMAH(acc[nt], al0, al1, al2, al3, FB[nt].x, FB[nt].y);                \
        }                                                                         \
        if ((jj) + 2 < 4) {                                                       \
            _Pragma("unroll")                                                     \
            for (int nt = 0; nt < 4; nt++)                                        \
                FB[nt] = pb[((((jj) + 2) * 4 + nt) << 5)];                        \
        }                                                                         \
    }

    STEP(0, fbA)
    STEP(1, fbB)
    STEP(2, fbA)
    STEP(3, fbB)
    #undef STEP

    // ---- merge the 4 k-groups (reuse Asm) ----
    __syncthreads();
    float* red = Asm;   // [3][2][32][16] = 12 KB
    if (kg != 0) {
        #pragma unroll
        for (int nt = 0; nt < 4; nt++)
            #pragma unroll
            for (int i = 0; i < 4; i++)
                red[(((kg - 1) * 2 + rtile) * 32 + lane) * 16 + nt * 4 + i] = acc[nt][i];
    }
    __syncthreads();

    if (kg == 0) {
        #pragma unroll
        for (int g = 0; g < 3; g++)
            #pragma unroll
            for (int nt = 0; nt < 4; nt++)
                #pragma unroll
                for (int i = 0; i < 4; i++)
                    acc[nt][i] += red[((g * 2 + rtile) * 32 + lane) * 16 + nt * 4 + i];

        const int r0 = n0 + rtile * 16 + (lane >> 2);
        #pragma unroll
        for (int nt = 0; nt < 4; nt++) {
            int col = nt * 8 + 2 * (lane & 3);
            float2 cc = *(const float2*)(g_c + col);
            float2 v0 = make_float2(acc[nt][0] * (1.0f / 256.0f) + cc.x,
                                    acc[nt][1] * (1.0f / 256.0f) + cc.y);
            float2 v1 = make_float2(acc[nt][2] * (1.0f / 256.0f) + cc.x,
                                    acc[nt][3] * (1.0f / 256.0f) + cc.y);
            *(float2*)(out + (size_t)r0 * D_LAT + col)       = v0;
            *(float2*)(out + (size_t)(r0 + 8) * D_LAT + col) = v1;
        }
    }
}

extern "C" void kernel_launch(void* const* d_in, const int* in_sizes, int n_in,
                              void* d_out, int out_size)
{
    const float* embeds     = (const float*)d_in[0];
    const float* dists      = (const float*)d_in[1];
    const float* W_hidden   = (const float*)d_in[2];
    const float* b_hidden   = (const float*)d_in[3];
    const int*   anchor_ids = (const int*)  d_in[4];
    float*       out        = (float*)d_out;

    cudaFuncSetAttribute(pnn_mma_kernel,
                         cudaFuncAttributeMaxDynamicSharedMemorySize, SMEM_B);

    precompute_kernel<<<9, 256>>>(embeds, W_hidden, b_hidden, anchor_ids);

    cudaLaunchConfig_t cfg = {};
    cfg.gridDim  = dim3(N_NODES / 32, 1, 1);
    cfg.blockDim = dim3(256, 1, 1);
    cfg.dynamicSmemBytes = SMEM_B;
    cfg.stream = 0;
    cudaLaunchAttribute attr[1];
    attr[0].id = cudaLaunchAttributeProgrammaticStreamSerialization;
    attr[0].val.programmaticStreamSerializationAllowed = 1;
    cfg.attrs = attr;
    cfg.numAttrs = 1;

    cudaError_t e = cudaLaunchKernelEx(&cfg, pnn_mma_kernel, dists, out);
    if (e != cudaSuccess) {
        pnn_mma_kernel<<<N_NODES / 32, 256, SMEM_B>>>(dists, out);
    }
}